// round 3
// baseline (speedup 1.0000x reference)
#include <cuda_runtime.h>

// APPNP, K=10:  g_{t+1} = 0.9*norm^2 * (sum_{(s->v) in E} g_t[s]) + 0.1*norm*feat0
// where g = norm ⊙ h. Final: h = 0.9*norm*agg + 0.1*feat0.
//
// CSR gather (edges counting-sorted by dst), zero atomics in the hot loop.
// Round-3 restructure: 16 lanes per node (warp = 2 nodes), float4 per lane,
// and batch-8 load bursts for MLP=8 on the random row gathers.

#define NMAX  100000
#define DF    64
#define DF4   (DF / 4)
#define EMAX  1000000
#define KITER 10
#define SCAN_T 1024

__device__ float g_a[NMAX * DF];     // ping
__device__ float g_b[NMAX * DF];     // pong
__device__ float g_norm[NMAX];
__device__ int   g_deg[NMAX];
__device__ int   g_rowptr[NMAX + 1];
__device__ int   g_cursor[NMAX];
__device__ int   g_srcs[EMAX];       // src ids sorted by dst bucket

// ---------------------------------------------------------------- build ----

__global__ void k_zero(int n) {
    int i = blockIdx.x * blockDim.x + threadIdx.x;
    if (i < n) { g_deg[i] = 0; g_cursor[i] = 0; }
}

__global__ void k_deg(const int* __restrict__ dst, int e) {
    int i = blockIdx.x * blockDim.x + threadIdx.x;
    if (i < e) atomicAdd(&g_deg[dst[i]], 1);
}

// Single-block exclusive scan of g_deg -> g_rowptr; also norm = deg^{-1/2}.
__global__ void k_scan(int n, int e) {
    __shared__ int sums[SCAN_T];
    int t = threadIdx.x;
    int chunk = (n + SCAN_T - 1) / SCAN_T;
    int start = t * chunk;
    int end   = min(start + chunk, n);
    int s = 0;
    for (int i = start; i < end; ++i) s += g_deg[i];
    sums[t] = s;
    __syncthreads();
    for (int off = 1; off < SCAN_T; off <<= 1) {
        int x = (t >= off) ? sums[t - off] : 0;
        __syncthreads();
        sums[t] += x;
        __syncthreads();
    }
    int run = sums[t] - s;  // exclusive prefix of my chunk
    for (int i = start; i < end; ++i) {
        int d = g_deg[i];
        g_rowptr[i] = run;
        g_norm[i]   = rsqrtf(fmaxf((float)d, 1.0f));
        run += d;
    }
    if (t == 0) g_rowptr[n] = e;
}

__global__ void k_fill(const int* __restrict__ src,
                       const int* __restrict__ dst, int e) {
    int i = blockIdx.x * blockDim.x + threadIdx.x;
    if (i < e) {
        int d = dst[i];
        int pos = g_rowptr[d] + atomicAdd(&g_cursor[d], 1);
        g_srcs[pos] = src[i];
    }
}

// g_0 = norm ⊙ feat  (into g_a)
__global__ void k_init(const float* __restrict__ feat, int n) {
    int i = blockIdx.x * blockDim.x + threadIdx.x;
    if (i < n * DF4) {
        int row = i >> 4;
        float nm = g_norm[row];
        float4 f = reinterpret_cast<const float4*>(feat)[i];
        f.x *= nm; f.y *= nm; f.z *= nm; f.w *= nm;
        reinterpret_cast<float4*>(g_a)[i] = f;
    }
}

// ----------------------------------------------------------------- loop ----

// Warp covers 2 destination nodes: lanes [0,16) -> node 2w, lanes [16,32) ->
// node 2w+1. Each lane owns one float4 (16B); a node's 256B row is one
// coalesced 16-lane LDG.128 group per edge. Edges are consumed in bursts of
// 8: all 8 row loads issued back-to-back into registers (MLP=8), then summed.
__global__ void k_prop(const float* __restrict__ feat,
                       float* __restrict__ out,
                       int n, int flip, int last) {
    int gt   = blockIdx.x * blockDim.x + threadIdx.x;
    int lane = gt & 31;
    int half = lane >> 4;               // which node within the warp
    int l16  = lane & 15;               // lane within the 16-lane group
    int v    = ((gt >> 5) << 1) + half; // node id
    if (v >= n) return;

    const float4* gin  = reinterpret_cast<const float4*>(flip ? g_b : g_a);
    float4*       gout = reinterpret_cast<float4*>(flip ? g_a : g_b);

    int start = g_rowptr[v];
    int end   = g_rowptr[v + 1];

    float ax = 0.f, ay = 0.f, az = 0.f, aw = 0.f;

    for (int base = start; base < end; base += 16) {
        int idx = base + l16;
        int s   = (idx < end) ? g_srcs[idx] : 0;   // 16 src ids in regs
        int cnt = min(16, end - base);
        for (int j0 = 0; j0 < cnt; j0 += 8) {
            float4 vv[8];
            #pragma unroll
            for (int k = 0; k < 8; ++k) {
                int sk = __shfl_sync(0xffffffff, s, (half << 4) + j0 + k);
                if (j0 + k < cnt) {
                    vv[k] = gin[sk * DF4 + l16];
                } else {
                    vv[k] = make_float4(0.f, 0.f, 0.f, 0.f);
                }
            }
            #pragma unroll
            for (int k = 0; k < 8; ++k) {
                ax += vv[k].x; ay += vv[k].y; az += vv[k].z; aw += vv[k].w;
            }
        }
    }

    float nm = g_norm[v];
    float4 f = reinterpret_cast<const float4*>(feat)[v * DF4 + l16];
    float4 o;
    if (!last) {
        float c1 = 0.9f * nm * nm;
        float c2 = 0.1f * nm;
        o.x = c1 * ax + c2 * f.x;
        o.y = c1 * ay + c2 * f.y;
        o.z = c1 * az + c2 * f.z;
        o.w = c1 * aw + c2 * f.w;
        gout[v * DF4 + l16] = o;
    } else {
        float c1 = 0.9f * nm;
        o.x = c1 * ax + 0.1f * f.x;
        o.y = c1 * ay + 0.1f * f.y;
        o.z = c1 * az + 0.1f * f.z;
        o.w = c1 * aw + 0.1f * f.w;
        reinterpret_cast<float4*>(out)[v * DF4 + l16] = o;
    }
}

// ---------------------------------------------------------------- launch ----

extern "C" void kernel_launch(void* const* d_in, const int* in_sizes, int n_in,
                              void* d_out, int out_size) {
    const float* feat = (const float*)d_in[0];
    const int*   src  = (const int*)d_in[1];
    const int*   dst  = (const int*)d_in[2];
    float*       out  = (float*)d_out;

    int n = in_sizes[0] / DF;   // 100000
    int e = in_sizes[1];        // 1000000

    const int T = 256;
    int blk_n   = (n + T - 1) / T;
    int blk_e   = (e + T - 1) / T;
    int blk_nd4 = (n * DF4 + T - 1) / T;
    int blk_p   = (n * 16 + T - 1) / T;     // 16 lanes per node

    // CSR build (per call; graph-capturable, no allocs)
    k_zero<<<blk_n, T>>>(n);
    k_deg<<<blk_e, T>>>(dst, e);
    k_scan<<<1, SCAN_T>>>(n, e);
    k_fill<<<blk_e, T>>>(src, dst, e);
    k_init<<<blk_nd4, T>>>(feat, n);

    // Propagation: ping-pong g_a <-> g_b, final iter writes d_out.
    for (int t = 0; t < KITER; ++t) {
        int flip = t & 1;
        int last = (t == KITER - 1);
        k_prop<<<blk_p, T>>>(feat, out, n, flip, last);
    }
}

// round 4
// speedup vs baseline: 1.2878x; 1.2878x over previous
#include <cuda_runtime.h>

// APPNP, K=10:  g_{t+1} = 0.9*norm^2 * (sum_{(s->v) in E} g_t[s]) + 0.1*norm*feat0
// where g = norm ⊙ h. Final: h = 0.9*norm*agg + 0.1*feat0.
//
// CSR gather (edges counting-sorted by dst), zero atomics in the hot loop.
// Round 4: one warp per node (uniform loop bounds, no divergence), float2 per
// lane (256B row per warp-load), edges consumed in bursts of 8 with src ids
// fetched via uniform broadcast loads (no shuffle chain) -> MLP ~8.

#define NMAX  100000
#define DF    64
#define DF2   (DF / 2)
#define DF4   (DF / 4)
#define EMAX  1000000
#define KITER 10
#define SCAN_T 1024

__device__ float g_a[NMAX * DF];     // ping
__device__ float g_b[NMAX * DF];     // pong
__device__ float g_norm[NMAX];
__device__ int   g_deg[NMAX];
__device__ int   g_rowptr[NMAX + 1];
__device__ int   g_cursor[NMAX];
__device__ int   g_srcs[EMAX];       // src ids sorted by dst bucket

// ---------------------------------------------------------------- build ----

__global__ void k_zero(int n) {
    int i = blockIdx.x * blockDim.x + threadIdx.x;
    if (i < n) { g_deg[i] = 0; g_cursor[i] = 0; }
}

__global__ void k_deg(const int* __restrict__ dst, int e) {
    int i = blockIdx.x * blockDim.x + threadIdx.x;
    if (i < e) atomicAdd(&g_deg[dst[i]], 1);
}

// Single-block exclusive scan of g_deg -> g_rowptr; also norm = deg^{-1/2}.
__global__ void k_scan(int n, int e) {
    __shared__ int sums[SCAN_T];
    int t = threadIdx.x;
    int chunk = (n + SCAN_T - 1) / SCAN_T;
    int start = t * chunk;
    int end   = min(start + chunk, n);
    int s = 0;
    for (int i = start; i < end; ++i) s += g_deg[i];
    sums[t] = s;
    __syncthreads();
    for (int off = 1; off < SCAN_T; off <<= 1) {
        int x = (t >= off) ? sums[t - off] : 0;
        __syncthreads();
        sums[t] += x;
        __syncthreads();
    }
    int run = sums[t] - s;  // exclusive prefix of my chunk
    for (int i = start; i < end; ++i) {
        int d = g_deg[i];
        g_rowptr[i] = run;
        g_norm[i]   = rsqrtf(fmaxf((float)d, 1.0f));
        run += d;
    }
    if (t == 0) g_rowptr[n] = e;
}

__global__ void k_fill(const int* __restrict__ src,
                       const int* __restrict__ dst, int e) {
    int i = blockIdx.x * blockDim.x + threadIdx.x;
    if (i < e) {
        int d = dst[i];
        int pos = g_rowptr[d] + atomicAdd(&g_cursor[d], 1);
        g_srcs[pos] = src[i];
    }
}

// g_0 = norm ⊙ feat  (into g_a)
__global__ void k_init(const float* __restrict__ feat, int n) {
    int i = blockIdx.x * blockDim.x + threadIdx.x;
    if (i < n * DF4) {
        int row = i >> 4;
        float nm = g_norm[row];
        float4 f = reinterpret_cast<const float4*>(feat)[i];
        f.x *= nm; f.y *= nm; f.z *= nm; f.w *= nm;
        reinterpret_cast<float4*>(g_a)[i] = f;
    }
}

// ----------------------------------------------------------------- loop ----

// One warp per destination node; lane owns 2 columns (float2). All lanes load
// the same g_srcs word (uniform broadcast), so id fetches are independent and
// shuffle-free. Row loads are issued in bursts of 8 for MLP.
__global__ void k_prop(const float* __restrict__ feat,
                       float* __restrict__ out,
                       int n, int flip, int last) {
    int gt   = blockIdx.x * blockDim.x + threadIdx.x;
    int v    = gt >> 5;
    int lane = gt & 31;
    if (v >= n) return;

    const float2* gin  = reinterpret_cast<const float2*>(flip ? g_b : g_a);
    float2*       gout = reinterpret_cast<float2*>(flip ? g_a : g_b);

    int idx = g_rowptr[v];
    int end = g_rowptr[v + 1];

    float ax = 0.f, ay = 0.f;

    // burst of 8 edges
    for (; idx + 8 <= end; idx += 8) {
        int s[8];
        #pragma unroll
        for (int k = 0; k < 8; ++k) s[k] = __ldg(&g_srcs[idx + k]);
        float2 vv[8];
        #pragma unroll
        for (int k = 0; k < 8; ++k) vv[k] = gin[s[k] * DF2 + lane];
        #pragma unroll
        for (int k = 0; k < 8; ++k) { ax += vv[k].x; ay += vv[k].y; }
    }
    // burst of 4
    if (idx + 4 <= end) {
        int s[4];
        #pragma unroll
        for (int k = 0; k < 4; ++k) s[k] = __ldg(&g_srcs[idx + k]);
        float2 vv[4];
        #pragma unroll
        for (int k = 0; k < 4; ++k) vv[k] = gin[s[k] * DF2 + lane];
        #pragma unroll
        for (int k = 0; k < 4; ++k) { ax += vv[k].x; ay += vv[k].y; }
        idx += 4;
    }
    // tail
    for (; idx < end; ++idx) {
        int s0 = __ldg(&g_srcs[idx]);
        float2 v0 = gin[s0 * DF2 + lane];
        ax += v0.x; ay += v0.y;
    }

    float nm = g_norm[v];
    float2 f = reinterpret_cast<const float2*>(feat)[v * DF2 + lane];
    float2 o;
    if (!last) {
        float c1 = 0.9f * nm * nm;
        float c2 = 0.1f * nm;
        o.x = c1 * ax + c2 * f.x;
        o.y = c1 * ay + c2 * f.y;
        gout[v * DF2 + lane] = o;
    } else {
        float c1 = 0.9f * nm;
        o.x = c1 * ax + 0.1f * f.x;
        o.y = c1 * ay + 0.1f * f.y;
        reinterpret_cast<float2*>(out)[v * DF2 + lane] = o;
    }
}

// ---------------------------------------------------------------- launch ----

extern "C" void kernel_launch(void* const* d_in, const int* in_sizes, int n_in,
                              void* d_out, int out_size) {
    const float* feat = (const float*)d_in[0];
    const int*   src  = (const int*)d_in[1];
    const int*   dst  = (const int*)d_in[2];
    float*       out  = (float*)d_out;

    int n = in_sizes[0] / DF;   // 100000
    int e = in_sizes[1];        // 1000000

    const int T = 256;
    int blk_n   = (n + T - 1) / T;
    int blk_e   = (e + T - 1) / T;
    int blk_nd4 = (n * DF4 + T - 1) / T;
    int blk_p   = (n * 32 + T - 1) / T;     // warp per node

    // CSR build (per call; graph-capturable, no allocs)
    k_zero<<<blk_n, T>>>(n);
    k_deg<<<blk_e, T>>>(dst, e);
    k_scan<<<1, SCAN_T>>>(n, e);
    k_fill<<<blk_e, T>>>(src, dst, e);
    k_init<<<blk_nd4, T>>>(feat, n);

    // Propagation: ping-pong g_a <-> g_b, final iter writes d_out.
    for (int t = 0; t < KITER; ++t) {
        int flip = t & 1;
        int last = (t == KITER - 1);
        k_prop<<<blk_p, T>>>(feat, out, n, flip, last);
    }
}